// round 13
// baseline (speedup 1.0000x reference)
#include <cuda_runtime.h>
#include <cuda_bf16.h>
#include <cuda_fp16.h>
#include <math.h>
#include <stdint.h>

#define Bb 16
#define Hh 512
#define Ll 4096
#define NC 4096
#define LAMBDA 0.001f

// Scratch (no runtime allocation allowed)
__device__ float4   g_Tab[(size_t)Hh * 4096];               // per-POSITION pointwise table
__device__ uint32_t g_Yhi[(size_t)Bb * Hh * Ll / 2];        // fp16x2 of gelu(conv+skip)
__device__ uint32_t g_Whi[Hh * Hh / 2];                     // W fp16x2, row-major [v][k]

__device__ __forceinline__ float2 cadd(float2 a, float2 b) { return make_float2(a.x + b.x, a.y + b.y); }
__device__ __forceinline__ float2 csub(float2 a, float2 b) { return make_float2(a.x - b.x, a.y - b.y); }
__device__ __forceinline__ float2 cmul(float2 a, float2 b) {
    return make_float2(a.x * b.x - a.y * b.y, a.x * b.y + a.y * b.x);
}
__device__ __forceinline__ float2 conjf2(float2 a) { return make_float2(a.x, -a.y); }
__device__ __forceinline__ float2 cscale(float2 a, float s) { return make_float2(a.x * s, a.y * s); }

__device__ __forceinline__ int sidx(int n) { return n + (n >> 4); }
#define SMSZ (4096 + 256)

// 4-digit octal reversal (12-bit), involutive
__device__ __forceinline__ int rev4(int k) {
    return ((k & 7) << 9) | (((k >> 3) & 7) << 6) | (((k >> 6) & 7) << 3) | ((k >> 9) & 7);
}

// ---------------------------------------------------------------------------
// radix-8 butterfly + tree-depth twiddles
// ---------------------------------------------------------------------------
template <bool INV>
__device__ __forceinline__ void radix8(float2 a[8]) {
    const float C = 0.70710678118654752440f;
    float2 t0 = cadd(a[0], a[4]);
    float2 t1 = csub(a[0], a[4]);
    float2 t2 = cadd(a[2], a[6]);
    float2 t3;
    { float2 d = csub(a[2], a[6]); t3 = INV ? make_float2(-d.y, d.x) : make_float2(d.y, -d.x); }
    float2 E0 = cadd(t0, t2), E2 = csub(t0, t2);
    float2 E1 = cadd(t1, t3), E3 = csub(t1, t3);
    float2 s0 = cadd(a[1], a[5]);
    float2 s1 = csub(a[1], a[5]);
    float2 s2 = cadd(a[3], a[7]);
    float2 s3;
    { float2 d = csub(a[3], a[7]); s3 = INV ? make_float2(-d.y, d.x) : make_float2(d.y, -d.x); }
    float2 O0 = cadd(s0, s2), O2 = csub(s0, s2);
    float2 O1 = cadd(s1, s3), O3 = csub(s1, s3);
    float2 O1w, O2w, O3w;
    if (!INV) {
        O1w = make_float2(C * (O1.x + O1.y), C * (O1.y - O1.x));
        O2w = make_float2(O2.y, -O2.x);
        O3w = make_float2(C * (O3.y - O3.x), -C * (O3.x + O3.y));
    } else {
        O1w = make_float2(C * (O1.x - O1.y), C * (O1.y + O1.x));
        O2w = make_float2(-O2.y, O2.x);
        O3w = make_float2(-C * (O3.x + O3.y), C * (O3.x - O3.y));
    }
    a[0] = cadd(E0, O0);  a[4] = csub(E0, O0);
    a[1] = cadd(E1, O1w); a[5] = csub(E1, O1w);
    a[2] = cadd(E2, O2w); a[6] = csub(E2, O2w);
    a[3] = cadd(E3, O3w); a[7] = csub(E3, O3w);
}

// powers w^1..w^7 with dependency depth 3 (tree), ang = arg(w)
__device__ __forceinline__ void make_powers(float ang, float2 w[7]) {
    float sv, cv; __sincosf(ang, &sv, &cv);
    w[0] = make_float2(cv, sv);            // w1
    w[1] = cmul(w[0], w[0]);               // w2
    w[2] = cmul(w[1], w[0]);               // w3
    w[3] = cmul(w[1], w[1]);               // w4
    w[4] = cmul(w[3], w[0]);               // w5
    w[5] = cmul(w[3], w[1]);               // w6
    w[6] = cmul(w[3], w[2]);               // w7
}
__device__ __forceinline__ void apply_tw(float2 a[8], const float2 w[7]) {
#pragma unroll
    for (int i = 1; i < 8; i++) a[i] = cmul(a[i], w[i - 1]);
}

// single-channel stage (build_kf)
template <bool INV, int LOGS, bool POST>
__device__ __forceinline__ void stage_g(float2* z, int t) {
    constexpr int S = 1 << LOGS;
    int j = t & (S - 1);
    int base = ((t >> LOGS) << (LOGS + 3)) + j;
    float2 a[8];
#pragma unroll
    for (int i = 0; i < 8; i++) a[i] = z[sidx(base + i * S)];
    bool tw = (S > 1) && (j != 0);
    float2 w[7];
    if (tw) make_powers((INV ? 6.283185307179586f : -6.283185307179586f) * (float)j / (float)(8 * S), w);
    if (!POST && tw) apply_tw(a, w);
    radix8<INV>(a);
    if (POST && tw) apply_tw(a, w);
#pragma unroll
    for (int i = 0; i < 8; i++) z[sidx(base + i * S)] = a[i];
}

// dual-channel stage: same (j, base) for both; twiddles computed once
template <bool INV, int LOGS, bool POST>
__device__ __forceinline__ void stage_g2(float2* zA, float2* zB, int t) {
    constexpr int S = 1 << LOGS;
    int j = t & (S - 1);
    int base = ((t >> LOGS) << (LOGS + 3)) + j;
    float2 a[8], b[8];
#pragma unroll
    for (int i = 0; i < 8; i++) a[i] = zA[sidx(base + i * S)];
#pragma unroll
    for (int i = 0; i < 8; i++) b[i] = zB[sidx(base + i * S)];
    bool tw = (S > 1) && (j != 0);
    float2 w[7];
    if (tw) make_powers((INV ? 6.283185307179586f : -6.283185307179586f) * (float)j / (float)(8 * S), w);
    if (!POST && tw) { apply_tw(a, w); apply_tw(b, w); }
    radix8<INV>(a);
    radix8<INV>(b);
    if (POST && tw) { apply_tw(a, w); apply_tw(b, w); }
#pragma unroll
    for (int i = 0; i < 8; i++) zA[sidx(base + i * S)] = a[i];
#pragma unroll
    for (int i = 0; i < 8; i++) zB[sidx(base + i * S)] = b[i];
}

// ---------------------------------------------------------------------------
// Kernel A: squash + DIF rfft(8192 packed) -> per-position table g_Tab
// ---------------------------------------------------------------------------
__global__ __launch_bounds__(512, 2) void build_kf_kernel(const float* __restrict__ kparam) {
    __shared__ float2 z[SMSZ];
    int t = threadIdx.x, h = blockIdx.x;
    const float2* kp2 = (const float2*)(kparam + (size_t)h * Ll);

    {
        float2 a[8];
#pragma unroll
        for (int i = 0; i < 4; i++) {
            float2 v = kp2[t + 512 * i];
            float s0 = fabsf(v.x) - LAMBDA; float aa = (s0 > 0.f) ? copysignf(s0, v.x) : 0.f;
            float s1 = fabsf(v.y) - LAMBDA; float bb = (s1 > 0.f) ? copysignf(s1, v.y) : 0.f;
            a[i] = make_float2(aa, bb);
        }
#pragma unroll
        for (int i = 4; i < 8; i++) a[i] = make_float2(0.f, 0.f);
        radix8<false>(a);
        if (t) { float2 w[7]; make_powers(-6.283185307179586f * (float)t / 4096.0f, w); apply_tw(a, w); }
#pragma unroll
        for (int i = 0; i < 8; i++) z[sidx(t + i * 512)] = a[i];
    }
    __syncthreads();
    stage_g<false, 6, true>(z, t); __syncthreads();
    stage_g<false, 3, true>(z, t); __syncthreads();
    stage_g<false, 0, true>(z, t); __syncthreads();

    float4* tab = g_Tab + (size_t)h * 4096;
    const float scale = 1.0f / (float)NC;
    for (int p = t; p < 4096; p += 512) {
        int k = rev4(p);
        float4 e;
        if (k == 0) {
            float2 Z0 = z[sidx(0)];
            float K0 = (Z0.x + Z0.y) * scale;
            float KN = (Z0.x - Z0.y) * scale;
            e = make_float4(0.5f * (K0 + KN), 0.f, 0.f, 0.5f * (K0 - KN));
        } else {
            int kk = (k <= 2048) ? k : 4096 - k;
            float2 Zk = z[sidx(rev4(kk))];
            float2 Zj = z[sidx(rev4(4096 - kk))];
            float2 E = make_float2(0.5f * (Zk.x + Zj.x),  0.5f * (Zk.y - Zj.y));
            float2 O = make_float2(0.5f * (Zk.y + Zj.y), -0.5f * (Zk.x - Zj.x));
            float sv, cv; __sincosf(-3.14159265358979f * (float)kk / (float)NC, &sv, &cv);
            float2 W  = make_float2(cv, sv);
            float2 Wj = make_float2(-cv, sv);
            float2 Kk = cscale(cadd(E, cmul(W, O)), scale);
            float2 Kj = cscale(cadd(conjf2(E), cmul(Wj, conjf2(O))), scale);
            float s = sv, c = cv;
            if (k <= 2048) {
                e.x = 0.5f * ((1.f + s) * Kk.x + (1.f - s) * Kj.x);
                e.y = 0.5f * ((1.f + s) * Kk.y - (1.f - s) * Kj.y);
                e.z = -0.5f * c * (Kk.y + Kj.y);
                e.w =  0.5f * c * (Kk.x - Kj.x);
            } else {
                e.x = 0.5f * ((1.f + s) * Kj.x + (1.f - s) * Kk.x);
                e.y = 0.5f * ((1.f + s) * Kj.y - (1.f - s) * Kk.y);
                e.z =  0.5f * c * (Kj.y + Kk.y);
                e.w = -0.5f * c * (Kj.x - Kk.x);
            }
        }
        tab[p] = e;
    }
}

// ---------------------------------------------------------------------------
// Kernel A2: W fp32 -> fp16 (once)
// ---------------------------------------------------------------------------
__global__ void split_w_kernel(const float* __restrict__ W) {
    int i = blockIdx.x * 256 + threadIdx.x;
    float4 w4 = *(const float4*)(W + 4 * (size_t)i);
    __half h0 = __float2half(w4.x);
    __half h1 = __float2half(w4.y);
    __half h2 = __float2half(w4.z);
    __half h3 = __float2half(w4.w);
    uint2 hp;
    hp.x = (uint32_t)__half_as_ushort(h0) | ((uint32_t)__half_as_ushort(h1) << 16);
    hp.y = (uint32_t)__half_as_ushort(h2) | ((uint32_t)__half_as_ushort(h3) << 16);
    *(uint2*)(g_Whi + 2 * (size_t)i) = hp;
}

// ---------------------------------------------------------------------------
// Kernel B: TWO channels (b0, b0+1) per CTA, same h. 3 smem buffers.
//   fwd (dual) -> pw A: z1->z3 -> pw B: z2->z1 -> inv (dual: z3, z1)
//   -> last stage in regs -> +D*u -> GELU -> fp16
// ---------------------------------------------------------------------------
#define CONV_SMEM (3 * SMSZ * (int)sizeof(float2))   // 104448

__device__ __forceinline__ void pointwise_pass(const float4* __restrict__ tab,
                                               const float2* __restrict__ src,
                                               float2* __restrict__ dst, int t) {
    for (int p = t; p < 4096; p += 512) {
        int q = rev4((4096 - rev4(p)) & 4095);
        float2 Zp = src[sidx(p)];
        float2 Zq = src[sidx(q)];
        float4 tA = tab[p];
        float nx = tA.x * Zp.x - tA.y * Zp.y + tA.z * Zq.x + tA.w * Zq.y;
        float ny = tA.x * Zp.y + tA.y * Zp.x + tA.w * Zq.x - tA.z * Zq.y;
        dst[sidx(p)] = make_float2(nx, ny);
    }
}

__global__ __launch_bounds__(512, 2) void conv_kernel(const float* __restrict__ u,
                                                      const float* __restrict__ D) {
    extern __shared__ float2 zz[];
    float2* z1 = zz;
    float2* z2 = zz + SMSZ;
    float2* z3 = zz + 2 * SMSZ;
    int t = threadIdx.x, h = blockIdx.x;
    int b0 = 2 * blockIdx.y, b1 = b0 + 1;
    const float2* uA = (const float2*)(u + ((size_t)(b0 * Hh + h)) * Ll);
    const float2* uB = (const float2*)(u + ((size_t)(b1 * Hh + h)) * Ll);

    // forward first stage (dual, twiddles shared)
    {
        float2 a[8], bb[8];
#pragma unroll
        for (int i = 0; i < 4; i++) { a[i] = uA[t + 512 * i]; bb[i] = uB[t + 512 * i]; }
#pragma unroll
        for (int i = 4; i < 8; i++) { a[i] = make_float2(0.f, 0.f); bb[i] = make_float2(0.f, 0.f); }
        radix8<false>(a);
        radix8<false>(bb);
        if (t) {
            float2 w[7]; make_powers(-6.283185307179586f * (float)t / 4096.0f, w);
            apply_tw(a, w); apply_tw(bb, w);
        }
#pragma unroll
        for (int i = 0; i < 8; i++) z1[sidx(t + i * 512)] = a[i];
#pragma unroll
        for (int i = 0; i < 8; i++) z2[sidx(t + i * 512)] = bb[i];
    }
    __syncthreads();
    stage_g2<false, 6, true>(z1, z2, t); __syncthreads();
    stage_g2<false, 3, true>(z1, z2, t); __syncthreads();
    stage_g2<false, 0, true>(z1, z2, t); __syncthreads();

    const float4* tab = g_Tab + (size_t)h * 4096;
    pointwise_pass(tab, z1, z3, t);      // A: z1 -> z3
    __syncthreads();
    pointwise_pass(tab, z2, z1, t);      // B: z2 -> z1
    __syncthreads();

    // inverse (dual): A on z3, B on z1
    stage_g2<true, 0, false>(z3, z1, t); __syncthreads();
    stage_g2<true, 3, false>(z3, z1, t); __syncthreads();
    stage_g2<true, 6, false>(z3, z1, t); __syncthreads();

    // last inverse stage in registers + epilogue (twiddles shared)
    float2 w[7];
    bool have_w = (t != 0);
    if (have_w) make_powers(6.283185307179586f * (float)t / 4096.0f, w);

    float dcoefA = D[h];   // same h for both channels
    const float INV_SQRT2 = 0.70710678118654752f;

#pragma unroll
    for (int ch = 0; ch < 2; ch++) {
        const float2* u2 = ch ? uB : uA;
        const float2* zs = ch ? z1 : z3;
        uint32_t* yh = g_Yhi + ((size_t)((ch ? b1 : b0) * Hh + h)) * (Ll / 2);
        float2 a[8];
#pragma unroll
        for (int i = 0; i < 8; i++) a[i] = zs[sidx(t + i * 512)];
        if (have_w) apply_tw(a, w);
        radix8<true>(a);
#pragma unroll
        for (int i = 0; i < 4; i++) {
            int n = t + 512 * i;
            float2 uv = u2[n];
            float y0 = a[i].x + dcoefA * uv.x;
            float y1 = a[i].y + dcoefA * uv.y;
            y0 = 0.5f * y0 * (1.0f + erff(y0 * INV_SQRT2));
            y1 = 0.5f * y1 * (1.0f + erff(y1 * INV_SQRT2));
            __half h0 = __float2half(y0);
            __half h1 = __float2half(y1);
            yh[n] = (uint32_t)__half_as_ushort(h0) | ((uint32_t)__half_as_ushort(h1) << 16);
        }
    }
}

// ---------------------------------------------------------------------------
// Kernel C: HMMA fp16 GEMM, single term (Whi*Yhi), warp tile 64x32,
// CTA 128x128, 8 warps 2x4, 3-stage cp.async pipeline (round-11 validated)
// ---------------------------------------------------------------------------
#define HC 32
#define NHC 16
#define A_ST 80
#define ST_SZ 18432
#define GEMM_SMEM (3 * ST_SZ)   // 55296

__device__ __forceinline__ uint32_t smem_u32(const void* p) {
    uint32_t a;
    asm("{ .reg .u64 t; cvta.to.shared.u64 t, %1; cvt.u32.u64 %0, t; }" : "=r"(a) : "l"(p));
    return a;
}
__device__ __forceinline__ void cpa16(uint32_t dst, const void* src) {
    asm volatile("cp.async.cg.shared.global [%0], [%1], 16;" :: "r"(dst), "l"(src));
}
__device__ __forceinline__ void ldsm4(uint32_t r[4], uint32_t addr) {
    asm volatile("ldmatrix.sync.aligned.m8n8.x4.shared.b16 {%0,%1,%2,%3}, [%4];"
                 : "=r"(r[0]), "=r"(r[1]), "=r"(r[2]), "=r"(r[3]) : "r"(addr));
}
__device__ __forceinline__ void ldsm4t(uint32_t r[4], uint32_t addr) {
    asm volatile("ldmatrix.sync.aligned.m8n8.x4.trans.shared.b16 {%0,%1,%2,%3}, [%4];"
                 : "=r"(r[0]), "=r"(r[1]), "=r"(r[2]), "=r"(r[3]) : "r"(addr));
}
__device__ __forceinline__ void mma16816h(float c[4], const uint32_t a[4], const uint32_t b[2]) {
    asm volatile(
        "mma.sync.aligned.m16n8k16.row.col.f32.f16.f16.f32 "
        "{%0,%1,%2,%3}, {%4,%5,%6,%7}, {%8,%9}, {%0,%1,%2,%3};"
        : "+f"(c[0]), "+f"(c[1]), "+f"(c[2]), "+f"(c[3])
        : "r"(a[0]), "r"(a[1]), "r"(a[2]), "r"(a[3]), "r"(b[0]), "r"(b[1]));
}
__device__ __forceinline__ float silu_f(float x) { return x / (1.0f + __expf(-x)); }
__device__ __forceinline__ int bswz(int k, int cb) { return (cb & 8) | ((cb ^ k) & 7); }

__global__ __launch_bounds__(256, 2) void gemm_silu_kernel(const float* __restrict__ bias,
                                                           float* __restrict__ out) {
    extern __shared__ char smem[];
    uint32_t sb = smem_u32(smem);
    int tid = threadIdx.x;
    int wid = tid >> 5;
    int lane = tid & 31;

    int v0 = blockIdx.x * 128;           // vt fastest -> 4 CTAs share B tile in L2
    int l0 = blockIdx.y * 128;
    int b  = blockIdx.z;

    int wm = wid & 1;
    int wn = wid >> 1;

    const __half* Yh = (const __half*)g_Yhi;
    const __half* Wh = (const __half*)g_Whi;

    float acc[4][4][4];
#pragma unroll
    for (int i = 0; i < 4; i++)
#pragma unroll
        for (int j = 0; j < 4; j++)
#pragma unroll
            for (int q = 0; q < 4; q++) acc[i][j][q] = 0.f;

    int ar  = tid >> 1;
    int ab  = (tid & 1) * 2;
    int bk  = tid >> 4;
    int bcb = tid & 15;

    auto load_hc = [&](int hc, int s) {
        int k0 = hc * HC;
        uint32_t base = sb + s * ST_SZ;
#pragma unroll
        for (int i = 0; i < 2; i++) {
            int blk = ab + i;
            size_t ga = (size_t)(v0 + ar) * Hh + k0 + blk * 8;
            cpa16(base + ar * A_ST + blk * 16, Wh + ga);
        }
#pragma unroll
        for (int g = 0; g < 2; g++) {
            int k = bk + g * 16;
            size_t ge = ((size_t)(b * Hh) + k0 + k) * Ll + l0 + bcb * 8;
            cpa16(base + 10240 + k * 256 + bswz(k, bcb) * 16, Yh + ge);
        }
    };

    load_hc(0, 0);
    asm volatile("cp.async.commit_group;" ::: "memory");
    load_hc(1, 1);
    asm volatile("cp.async.commit_group;" ::: "memory");

    for (int hc = 0; hc < NHC; hc++) {
        if (hc < NHC - 1) {
            asm volatile("cp.async.wait_group 1;" ::: "memory");
        } else {
            asm volatile("cp.async.wait_group 0;" ::: "memory");
        }
        __syncthreads();
        if (hc + 2 < NHC) {
            load_hc(hc + 2, (hc + 2) % 3);
            asm volatile("cp.async.commit_group;" ::: "memory");
        }

        uint32_t abase = sb + (hc % 3) * ST_SZ;
        uint32_t bbase = abase + 10240;
#pragma unroll
        for (int ks = 0; ks < 2; ks++) {
            uint32_t bh[2][4];
#pragma unroll
            for (int g = 0; g < 2; g++) {
                int krow = ks * 16 + (lane & 15);
                int cb = wn * 4 + g * 2 + (lane >> 4);
                uint32_t baddr = bbase + krow * 256 + bswz(krow, cb) * 16;
                ldsm4t(bh[g], baddr);
            }
#pragma unroll
            for (int mt = 0; mt < 4; mt++) {
                int arow = wm * 64 + mt * 16 + (lane & 15);
                uint32_t aaddr = abase + arow * A_ST + ks * 32 + (lane >> 4) * 16;
                uint32_t ahf[4];
                ldsm4(ahf, aaddr);
#pragma unroll
                for (int nt = 0; nt < 4; nt++) {
                    const uint32_t* bhx = &bh[nt >> 1][(nt & 1) * 2];
                    mma16816h(acc[mt][nt], ahf, bhx);
                }
            }
        }
    }

    __syncthreads();
    int g = lane >> 2;
    int cq = (lane & 3) * 2;
#pragma unroll
    for (int mt = 0; mt < 4; mt++) {
        int vbase = v0 + wm * 64 + mt * 16 + g;
        float bv0 = bias[vbase];
        float bv1 = bias[vbase + 8];
        float* row0 = out + ((size_t)(b * Hh) + vbase) * Ll;
        float* row1 = row0 + 8 * Ll;
#pragma unroll
        for (int nt = 0; nt < 4; nt++) {
            int lc = l0 + wn * 32 + nt * 8 + cq;
            float2 o0, o1;
            o0.x = silu_f(acc[mt][nt][0] + bv0);
            o0.y = silu_f(acc[mt][nt][1] + bv0);
            o1.x = silu_f(acc[mt][nt][2] + bv1);
            o1.y = silu_f(acc[mt][nt][3] + bv1);
            *(float2*)(row0 + lc) = o0;
            *(float2*)(row1 + lc) = o1;
        }
    }
}

extern "C" void kernel_launch(void* const* d_in, const int* in_sizes, int n_in,
                              void* d_out, int out_size) {
    const float* u    = (const float*)d_in[0];   // (16, 512, 4096)
    const float* kern = (const float*)d_in[1];   // (1, 512, 4096)
    const float* D    = (const float*)d_in[2];   // (1, 512)
    const float* Wout = (const float*)d_in[3];   // (512, 512)
    const float* bout = (const float*)d_in[4];   // (512,)
    float* out = (float*)d_out;                  // (16, 512, 4096)

    cudaFuncSetAttribute(gemm_silu_kernel, cudaFuncAttributeMaxDynamicSharedMemorySize, GEMM_SMEM);
    cudaFuncSetAttribute(conv_kernel, cudaFuncAttributeMaxDynamicSharedMemorySize, CONV_SMEM);

    build_kf_kernel<<<Hh, 512>>>(kern);
    split_w_kernel<<<256, 256>>>(Wout);
    conv_kernel<<<dim3(Hh, Bb / 2), 512, CONV_SMEM>>>(u, D);
    gemm_silu_kernel<<<dim3(4, 32, 16), 256, GEMM_SMEM>>>(bout, out);
}

// round 14
// speedup vs baseline: 1.0042x; 1.0042x over previous
#include <cuda_runtime.h>
#include <cuda_bf16.h>
#include <cuda_fp16.h>
#include <math.h>
#include <stdint.h>

#define Bb 16
#define Hh 512
#define Ll 4096
#define NC 4096
#define LAMBDA 0.001f

// Scratch (no runtime allocation allowed)
__device__ float4   g_Tab[(size_t)Hh * 4096];               // per-POSITION pointwise table
__device__ uint32_t g_Yhi[(size_t)Bb * Hh * Ll / 2];        // fp16x2 of gelu(conv+skip)
__device__ uint32_t g_Whi[Hh * Hh / 2];                     // W fp16x2, row-major [v][k]

__device__ __forceinline__ float2 cadd(float2 a, float2 b) { return make_float2(a.x + b.x, a.y + b.y); }
__device__ __forceinline__ float2 csub(float2 a, float2 b) { return make_float2(a.x - b.x, a.y - b.y); }
__device__ __forceinline__ float2 cmul(float2 a, float2 b) {
    return make_float2(a.x * b.x - a.y * b.y, a.x * b.y + a.y * b.x);
}
__device__ __forceinline__ float2 conjf2(float2 a) { return make_float2(a.x, -a.y); }
__device__ __forceinline__ float2 cscale(float2 a, float s) { return make_float2(a.x * s, a.y * s); }

__device__ __forceinline__ int sidx(int n) { return n + (n >> 4); }
#define SMSZ (4096 + 256)

// 4-digit octal reversal (12-bit), involutive
__device__ __forceinline__ int rev4(int k) {
    return ((k & 7) << 9) | (((k >> 3) & 7) << 6) | (((k >> 6) & 7) << 3) | ((k >> 9) & 7);
}

// ---------------------------------------------------------------------------
// radix-8 butterfly + tree-depth twiddles
// ---------------------------------------------------------------------------
template <bool INV>
__device__ __forceinline__ void radix8(float2 a[8]) {
    const float C = 0.70710678118654752440f;
    float2 t0 = cadd(a[0], a[4]);
    float2 t1 = csub(a[0], a[4]);
    float2 t2 = cadd(a[2], a[6]);
    float2 t3;
    { float2 d = csub(a[2], a[6]); t3 = INV ? make_float2(-d.y, d.x) : make_float2(d.y, -d.x); }
    float2 E0 = cadd(t0, t2), E2 = csub(t0, t2);
    float2 E1 = cadd(t1, t3), E3 = csub(t1, t3);
    float2 s0 = cadd(a[1], a[5]);
    float2 s1 = csub(a[1], a[5]);
    float2 s2 = cadd(a[3], a[7]);
    float2 s3;
    { float2 d = csub(a[3], a[7]); s3 = INV ? make_float2(-d.y, d.x) : make_float2(d.y, -d.x); }
    float2 O0 = cadd(s0, s2), O2 = csub(s0, s2);
    float2 O1 = cadd(s1, s3), O3 = csub(s1, s3);
    float2 O1w, O2w, O3w;
    if (!INV) {
        O1w = make_float2(C * (O1.x + O1.y), C * (O1.y - O1.x));
        O2w = make_float2(O2.y, -O2.x);
        O3w = make_float2(C * (O3.y - O3.x), -C * (O3.x + O3.y));
    } else {
        O1w = make_float2(C * (O1.x - O1.y), C * (O1.y + O1.x));
        O2w = make_float2(-O2.y, O2.x);
        O3w = make_float2(-C * (O3.x + O3.y), C * (O3.x - O3.y));
    }
    a[0] = cadd(E0, O0);  a[4] = csub(E0, O0);
    a[1] = cadd(E1, O1w); a[5] = csub(E1, O1w);
    a[2] = cadd(E2, O2w); a[6] = csub(E2, O2w);
    a[3] = cadd(E3, O3w); a[7] = csub(E3, O3w);
}

// powers w^1..w^7 with dependency depth 3 (tree)
__device__ __forceinline__ void make_powers(float ang, float2 w[7]) {
    float sv, cv; __sincosf(ang, &sv, &cv);
    w[0] = make_float2(cv, sv);
    w[1] = cmul(w[0], w[0]);
    w[2] = cmul(w[1], w[0]);
    w[3] = cmul(w[1], w[1]);
    w[4] = cmul(w[3], w[0]);
    w[5] = cmul(w[3], w[1]);
    w[6] = cmul(w[3], w[2]);
}
__device__ __forceinline__ void apply_tw(float2 a[8], const float2 w[7]) {
#pragma unroll
    for (int i = 1; i < 8; i++) a[i] = cmul(a[i], w[i - 1]);
}

template <bool INV, int LOGS, bool POST>
__device__ __forceinline__ void stage_g(float2* z, int t) {
    constexpr int S = 1 << LOGS;
    int j = t & (S - 1);
    int base = ((t >> LOGS) << (LOGS + 3)) + j;
    float2 a[8];
#pragma unroll
    for (int i = 0; i < 8; i++) a[i] = z[sidx(base + i * S)];
    bool tw = (S > 1) && (j != 0);
    float2 w[7];
    if (tw) make_powers((INV ? 6.283185307179586f : -6.283185307179586f) * (float)j / (float)(8 * S), w);
    if (!POST && tw) apply_tw(a, w);
    radix8<INV>(a);
    if (POST && tw) apply_tw(a, w);
#pragma unroll
    for (int i = 0; i < 8; i++) z[sidx(base + i * S)] = a[i];
}

// Forward DIF first stage specialized for zero-padded upper half (a[4..7]=0).
// Algebraically identical to radix8<false> with zeros + post-twiddle + store.
__device__ __forceinline__ void fwd_first_stage_z(float2* z, int t, const float2 in[4]) {
    const float C = 0.70710678118654752440f;
    float2 a0 = in[0], a1 = in[1], a2 = in[2], a3 = in[3];
    float2 r2 = make_float2(a2.y, -a2.x);   // -i * a2
    float2 E0 = cadd(a0, a2), E2 = csub(a0, a2);
    float2 E1 = cadd(a0, r2), E3 = csub(a0, r2);
    float2 r3 = make_float2(a3.y, -a3.x);   // -i * a3
    float2 O0 = cadd(a1, a3), O2 = csub(a1, a3);
    float2 O1 = cadd(a1, r3), O3 = csub(a1, r3);
    float2 O1w = make_float2(C * (O1.x + O1.y), C * (O1.y - O1.x));
    float2 O2w = make_float2(O2.y, -O2.x);
    float2 O3w = make_float2(C * (O3.y - O3.x), -C * (O3.x + O3.y));
    float2 o[8];
    o[0] = cadd(E0, O0);  o[4] = csub(E0, O0);
    o[1] = cadd(E1, O1w); o[5] = csub(E1, O1w);
    o[2] = cadd(E2, O2w); o[6] = csub(E2, O2w);
    o[3] = cadd(E3, O3w); o[7] = csub(E3, O3w);
    if (t) {
        float2 w[7]; make_powers(-6.283185307179586f * (float)t / 4096.0f, w);
        apply_tw(o, w);
    }
#pragma unroll
    for (int i = 0; i < 8; i++) z[sidx(t + i * 512)] = o[i];
}

// ---------------------------------------------------------------------------
// Kernel A: squash + DIF rfft(8192 packed) -> per-position table g_Tab
// ---------------------------------------------------------------------------
__global__ __launch_bounds__(512, 2) void build_kf_kernel(const float* __restrict__ kparam) {
    __shared__ float2 z[SMSZ];
    int t = threadIdx.x, h = blockIdx.x;
    const float2* kp2 = (const float2*)(kparam + (size_t)h * Ll);

    {
        float2 in[4];
#pragma unroll
        for (int i = 0; i < 4; i++) {
            float2 v = kp2[t + 512 * i];
            float s0 = fabsf(v.x) - LAMBDA; float aa = (s0 > 0.f) ? copysignf(s0, v.x) : 0.f;
            float s1 = fabsf(v.y) - LAMBDA; float bb = (s1 > 0.f) ? copysignf(s1, v.y) : 0.f;
            in[i] = make_float2(aa, bb);
        }
        fwd_first_stage_z(z, t, in);
    }
    __syncthreads();
    stage_g<false, 6, true>(z, t); __syncthreads();
    stage_g<false, 3, true>(z, t); __syncthreads();
    stage_g<false, 0, true>(z, t); __syncthreads();

    float4* tab = g_Tab + (size_t)h * 4096;
    const float scale = 1.0f / (float)NC;
    for (int p = t; p < 4096; p += 512) {
        int k = rev4(p);
        float4 e;
        if (k == 0) {
            float2 Z0 = z[sidx(0)];
            float K0 = (Z0.x + Z0.y) * scale;
            float KN = (Z0.x - Z0.y) * scale;
            e = make_float4(0.5f * (K0 + KN), 0.f, 0.f, 0.5f * (K0 - KN));
        } else {
            int kk = (k <= 2048) ? k : 4096 - k;
            float2 Zk = z[sidx(rev4(kk))];
            float2 Zj = z[sidx(rev4(4096 - kk))];
            float2 E = make_float2(0.5f * (Zk.x + Zj.x),  0.5f * (Zk.y - Zj.y));
            float2 O = make_float2(0.5f * (Zk.y + Zj.y), -0.5f * (Zk.x - Zj.x));
            float sv, cv; __sincosf(-3.14159265358979f * (float)kk / (float)NC, &sv, &cv);
            float2 W  = make_float2(cv, sv);
            float2 Wj = make_float2(-cv, sv);
            float2 Kk = cscale(cadd(E, cmul(W, O)), scale);
            float2 Kj = cscale(cadd(conjf2(E), cmul(Wj, conjf2(O))), scale);
            float s = sv, c = cv;
            if (k <= 2048) {
                e.x = 0.5f * ((1.f + s) * Kk.x + (1.f - s) * Kj.x);
                e.y = 0.5f * ((1.f + s) * Kk.y - (1.f - s) * Kj.y);
                e.z = -0.5f * c * (Kk.y + Kj.y);
                e.w =  0.5f * c * (Kk.x - Kj.x);
            } else {
                e.x = 0.5f * ((1.f + s) * Kj.x + (1.f - s) * Kk.x);
                e.y = 0.5f * ((1.f + s) * Kj.y - (1.f - s) * Kk.y);
                e.z =  0.5f * c * (Kj.y + Kk.y);
                e.w = -0.5f * c * (Kj.x - Kk.x);
            }
        }
        tab[p] = e;
    }
}

// ---------------------------------------------------------------------------
// Kernel A2: W fp32 -> fp16 (once)
// ---------------------------------------------------------------------------
__global__ void split_w_kernel(const float* __restrict__ W) {
    int i = blockIdx.x * 256 + threadIdx.x;
    float4 w4 = *(const float4*)(W + 4 * (size_t)i);
    __half h0 = __float2half(w4.x);
    __half h1 = __float2half(w4.y);
    __half h2 = __float2half(w4.z);
    __half h3 = __float2half(w4.w);
    uint2 hp;
    hp.x = (uint32_t)__half_as_ushort(h0) | ((uint32_t)__half_as_ushort(h1) << 16);
    hp.y = (uint32_t)__half_as_ushort(h2) | ((uint32_t)__half_as_ushort(h3) << 16);
    *(uint2*)(g_Whi + 2 * (size_t)i) = hp;
}

// ---------------------------------------------------------------------------
// Kernel B: DIF fwd -> per-position pointwise (z->z2) -> DIT inv (last stage
// in regs) -> +D*u -> GELU -> fp16   (round-11 structure; compute-trimmed)
// ---------------------------------------------------------------------------
#define CONV_SMEM (2 * SMSZ * (int)sizeof(float2))   // 69632

__global__ __launch_bounds__(512, 3) void conv_kernel(const float* __restrict__ u,
                                                      const float* __restrict__ D) {
    extern __shared__ float2 zz[];
    float2* z  = zz;
    float2* z2 = zz + SMSZ;
    int t = threadIdx.x, h = blockIdx.x, b = blockIdx.y;
    const float2* u2 = (const float2*)(u + ((size_t)(b * Hh + h)) * Ll);

    {
        float2 in[4];
#pragma unroll
        for (int i = 0; i < 4; i++) in[i] = u2[t + 512 * i];
        fwd_first_stage_z(z, t, in);
    }
    __syncthreads();
    stage_g<false, 6, true>(z, t); __syncthreads();
    stage_g<false, 3, true>(z, t); __syncthreads();
    stage_g<false, 0, true>(z, t); __syncthreads();

    const float4* tab = g_Tab + (size_t)h * 4096;
    for (int p = t; p < 4096; p += 512) {
        int q = rev4((4096 - rev4(p)) & 4095);
        float2 Zp = z[sidx(p)];
        float2 Zq = z[sidx(q)];
        float4 tA = tab[p];
        float nx = tA.x * Zp.x - tA.y * Zp.y + tA.z * Zq.x + tA.w * Zq.y;
        float ny = tA.x * Zp.y + tA.y * Zp.x + tA.w * Zq.x - tA.z * Zq.y;
        z2[sidx(p)] = make_float2(nx, ny);
    }
    __syncthreads();

    stage_g<true, 0, false>(z2, t); __syncthreads();
    stage_g<true, 3, false>(z2, t); __syncthreads();
    stage_g<true, 6, false>(z2, t); __syncthreads();

    float2 a[8];
#pragma unroll
    for (int i = 0; i < 8; i++) a[i] = z2[sidx(t + i * 512)];
    if (t) {
        float2 w[7]; make_powers(6.283185307179586f * (float)t / 4096.0f, w);
        apply_tw(a, w);
    }
    radix8<true>(a);

    float dcoef = D[h];
    uint32_t* yh = g_Yhi + ((size_t)(b * Hh + h)) * (Ll / 2);
    const float INV_SQRT2 = 0.70710678118654752f;
#pragma unroll
    for (int i = 0; i < 4; i++) {
        int n = t + 512 * i;
        float2 uv = u2[n];
        float y0 = a[i].x + dcoef * uv.x;
        float y1 = a[i].y + dcoef * uv.y;
        y0 = 0.5f * y0 * (1.0f + erff(y0 * INV_SQRT2));
        y1 = 0.5f * y1 * (1.0f + erff(y1 * INV_SQRT2));
        __half h0 = __float2half(y0);
        __half h1 = __float2half(y1);
        yh[n] = (uint32_t)__half_as_ushort(h0) | ((uint32_t)__half_as_ushort(h1) << 16);
    }
}

// ---------------------------------------------------------------------------
// Kernel C: HMMA fp16 GEMM, single term (Whi*Yhi), warp tile 64x32,
// CTA 128x128, 8 warps 2x4, 3-stage cp.async pipeline (round-11 validated)
// ---------------------------------------------------------------------------
#define HC 32
#define NHC 16
#define A_ST 80
#define ST_SZ 18432
#define GEMM_SMEM (3 * ST_SZ)   // 55296

__device__ __forceinline__ uint32_t smem_u32(const void* p) {
    uint32_t a;
    asm("{ .reg .u64 t; cvta.to.shared.u64 t, %1; cvt.u32.u64 %0, t; }" : "=r"(a) : "l"(p));
    return a;
}
__device__ __forceinline__ void cpa16(uint32_t dst, const void* src) {
    asm volatile("cp.async.cg.shared.global [%0], [%1], 16;" :: "r"(dst), "l"(src));
}
__device__ __forceinline__ void ldsm4(uint32_t r[4], uint32_t addr) {
    asm volatile("ldmatrix.sync.aligned.m8n8.x4.shared.b16 {%0,%1,%2,%3}, [%4];"
                 : "=r"(r[0]), "=r"(r[1]), "=r"(r[2]), "=r"(r[3]) : "r"(addr));
}
__device__ __forceinline__ void ldsm4t(uint32_t r[4], uint32_t addr) {
    asm volatile("ldmatrix.sync.aligned.m8n8.x4.trans.shared.b16 {%0,%1,%2,%3}, [%4];"
                 : "=r"(r[0]), "=r"(r[1]), "=r"(r[2]), "=r"(r[3]) : "r"(addr));
}
__device__ __forceinline__ void mma16816h(float c[4], const uint32_t a[4], const uint32_t b[2]) {
    asm volatile(
        "mma.sync.aligned.m16n8k16.row.col.f32.f16.f16.f32 "
        "{%0,%1,%2,%3}, {%4,%5,%6,%7}, {%8,%9}, {%0,%1,%2,%3};"
        : "+f"(c[0]), "+f"(c[1]), "+f"(c[2]), "+f"(c[3])
        : "r"(a[0]), "r"(a[1]), "r"(a[2]), "r"(a[3]), "r"(b[0]), "r"(b[1]));
}
__device__ __forceinline__ float silu_f(float x) { return x / (1.0f + __expf(-x)); }
__device__ __forceinline__ int bswz(int k, int cb) { return (cb & 8) | ((cb ^ k) & 7); }

__global__ __launch_bounds__(256, 2) void gemm_silu_kernel(const float* __restrict__ bias,
                                                           float* __restrict__ out) {
    extern __shared__ char smem[];
    uint32_t sb = smem_u32(smem);
    int tid = threadIdx.x;
    int wid = tid >> 5;
    int lane = tid & 31;

    int v0 = blockIdx.x * 128;           // vt fastest -> 4 CTAs share B tile in L2
    int l0 = blockIdx.y * 128;
    int b  = blockIdx.z;

    int wm = wid & 1;
    int wn = wid >> 1;

    const __half* Yh = (const __half*)g_Yhi;
    const __half* Wh = (const __half*)g_Whi;

    float acc[4][4][4];
#pragma unroll
    for (int i = 0; i < 4; i++)
#pragma unroll
        for (int j = 0; j < 4; j++)
#pragma unroll
            for (int q = 0; q < 4; q++) acc[i][j][q] = 0.f;

    int ar  = tid >> 1;
    int ab  = (tid & 1) * 2;
    int bk  = tid >> 4;
    int bcb = tid & 15;

    auto load_hc = [&](int hc, int s) {
        int k0 = hc * HC;
        uint32_t base = sb + s * ST_SZ;
#pragma unroll
        for (int i = 0; i < 2; i++) {
            int blk = ab + i;
            size_t ga = (size_t)(v0 + ar) * Hh + k0 + blk * 8;
            cpa16(base + ar * A_ST + blk * 16, Wh + ga);
        }
#pragma unroll
        for (int g = 0; g < 2; g++) {
            int k = bk + g * 16;
            size_t ge = ((size_t)(b * Hh) + k0 + k) * Ll + l0 + bcb * 8;
            cpa16(base + 10240 + k * 256 + bswz(k, bcb) * 16, Yh + ge);
        }
    };

    load_hc(0, 0);
    asm volatile("cp.async.commit_group;" ::: "memory");
    load_hc(1, 1);
    asm volatile("cp.async.commit_group;" ::: "memory");

    for (int hc = 0; hc < NHC; hc++) {
        if (hc < NHC - 1) {
            asm volatile("cp.async.wait_group 1;" ::: "memory");
        } else {
            asm volatile("cp.async.wait_group 0;" ::: "memory");
        }
        __syncthreads();
        if (hc + 2 < NHC) {
            load_hc(hc + 2, (hc + 2) % 3);
            asm volatile("cp.async.commit_group;" ::: "memory");
        }

        uint32_t abase = sb + (hc % 3) * ST_SZ;
        uint32_t bbase = abase + 10240;
#pragma unroll
        for (int ks = 0; ks < 2; ks++) {
            uint32_t bh[2][4];
#pragma unroll
            for (int g = 0; g < 2; g++) {
                int krow = ks * 16 + (lane & 15);
                int cb = wn * 4 + g * 2 + (lane >> 4);
                uint32_t baddr = bbase + krow * 256 + bswz(krow, cb) * 16;
                ldsm4t(bh[g], baddr);
            }
#pragma unroll
            for (int mt = 0; mt < 4; mt++) {
                int arow = wm * 64 + mt * 16 + (lane & 15);
                uint32_t aaddr = abase + arow * A_ST + ks * 32 + (lane >> 4) * 16;
                uint32_t ahf[4];
                ldsm4(ahf, aaddr);
#pragma unroll
                for (int nt = 0; nt < 4; nt++) {
                    const uint32_t* bhx = &bh[nt >> 1][(nt & 1) * 2];
                    mma16816h(acc[mt][nt], ahf, bhx);
                }
            }
        }
    }

    __syncthreads();
    int g = lane >> 2;
    int cq = (lane & 3) * 2;
#pragma unroll
    for (int mt = 0; mt < 4; mt++) {
        int vbase = v0 + wm * 64 + mt * 16 + g;
        float bv0 = bias[vbase];
        float bv1 = bias[vbase + 8];
        float* row0 = out + ((size_t)(b * Hh) + vbase) * Ll;
        float* row1 = row0 + 8 * Ll;
#pragma unroll
        for (int nt = 0; nt < 4; nt++) {
            int lc = l0 + wn * 32 + nt * 8 + cq;
            float2 o0, o1;
            o0.x = silu_f(acc[mt][nt][0] + bv0);
            o0.y = silu_f(acc[mt][nt][1] + bv0);
            o1.x = silu_f(acc[mt][nt][2] + bv1);
            o1.y = silu_f(acc[mt][nt][3] + bv1);
            *(float2*)(row0 + lc) = o0;
            *(float2*)(row1 + lc) = o1;
        }
    }
}

extern "C" void kernel_launch(void* const* d_in, const int* in_sizes, int n_in,
                              void* d_out, int out_size) {
    const float* u    = (const float*)d_in[0];   // (16, 512, 4096)
    const float* kern = (const float*)d_in[1];   // (1, 512, 4096)
    const float* D    = (const float*)d_in[2];   // (1, 512)
    const float* Wout = (const float*)d_in[3];   // (512, 512)
    const float* bout = (const float*)d_in[4];   // (512,)
    float* out = (float*)d_out;                  // (16, 512, 4096)

    cudaFuncSetAttribute(gemm_silu_kernel, cudaFuncAttributeMaxDynamicSharedMemorySize, GEMM_SMEM);
    cudaFuncSetAttribute(conv_kernel, cudaFuncAttributeMaxDynamicSharedMemorySize, CONV_SMEM);

    build_kf_kernel<<<Hh, 512>>>(kern);
    split_w_kernel<<<256, 256>>>(Wout);
    conv_kernel<<<dim3(Hh, Bb), 512, CONV_SMEM>>>(u, D);
    gemm_silu_kernel<<<dim3(4, 32, 16), 256, GEMM_SMEM>>>(bout, out);
}

// round 15
// speedup vs baseline: 1.0989x; 1.0943x over previous
#include <cuda_runtime.h>
#include <cuda_bf16.h>
#include <cuda_fp16.h>
#include <math.h>
#include <stdint.h>

#define Bb 16
#define Hh 512
#define Ll 4096
#define NC 4096
#define LAMBDA 0.001f

// Scratch (no runtime allocation allowed)
__device__ float4   g_Tab[(size_t)Hh * 4096];               // per-POSITION pointwise table
__device__ uint32_t g_Yhi[(size_t)Bb * Hh * Ll / 2];        // fp16x2 of gelu(conv+skip)
__device__ uint32_t g_Whi[Hh * Hh / 2];                     // W fp16x2, row-major [v][k]

__device__ __forceinline__ float2 cadd(float2 a, float2 b) { return make_float2(a.x + b.x, a.y + b.y); }
__device__ __forceinline__ float2 csub(float2 a, float2 b) { return make_float2(a.x - b.x, a.y - b.y); }
__device__ __forceinline__ float2 cmul(float2 a, float2 b) {
    return make_float2(a.x * b.x - a.y * b.y, a.x * b.y + a.y * b.x);
}
__device__ __forceinline__ float2 conjf2(float2 a) { return make_float2(a.x, -a.y); }
__device__ __forceinline__ float2 cscale(float2 a, float s) { return make_float2(a.x * s, a.y * s); }

__device__ __forceinline__ int sidx(int n) { return n + (n >> 4); }
#define SMSZ (4096 + 256)

// 4-digit octal reversal (12-bit), involutive
__device__ __forceinline__ int rev4(int k) {
    return ((k & 7) << 9) | (((k >> 3) & 7) << 6) | (((k >> 6) & 7) << 3) | ((k >> 9) & 7);
}

// ---------------------------------------------------------------------------
// radix-8 FFT machinery (round-11 validated; serial twiddle chain = low regs)
// ---------------------------------------------------------------------------
template <bool INV>
__device__ __forceinline__ void radix8(float2 a[8]) {
    const float C = 0.70710678118654752440f;
    float2 t0 = cadd(a[0], a[4]);
    float2 t1 = csub(a[0], a[4]);
    float2 t2 = cadd(a[2], a[6]);
    float2 t3;
    { float2 d = csub(a[2], a[6]); t3 = INV ? make_float2(-d.y, d.x) : make_float2(d.y, -d.x); }
    float2 E0 = cadd(t0, t2), E2 = csub(t0, t2);
    float2 E1 = cadd(t1, t3), E3 = csub(t1, t3);
    float2 s0 = cadd(a[1], a[5]);
    float2 s1 = csub(a[1], a[5]);
    float2 s2 = cadd(a[3], a[7]);
    float2 s3;
    { float2 d = csub(a[3], a[7]); s3 = INV ? make_float2(-d.y, d.x) : make_float2(d.y, -d.x); }
    float2 O0 = cadd(s0, s2), O2 = csub(s0, s2);
    float2 O1 = cadd(s1, s3), O3 = csub(s1, s3);
    float2 O1w, O2w, O3w;
    if (!INV) {
        O1w = make_float2(C * (O1.x + O1.y), C * (O1.y - O1.x));
        O2w = make_float2(O2.y, -O2.x);
        O3w = make_float2(C * (O3.y - O3.x), -C * (O3.x + O3.y));
    } else {
        O1w = make_float2(C * (O1.x - O1.y), C * (O1.y + O1.x));
        O2w = make_float2(-O2.y, O2.x);
        O3w = make_float2(-C * (O3.x + O3.y), C * (O3.x - O3.y));
    }
    a[0] = cadd(E0, O0);  a[4] = csub(E0, O0);
    a[1] = cadd(E1, O1w); a[5] = csub(E1, O1w);
    a[2] = cadd(E2, O2w); a[6] = csub(E2, O2w);
    a[3] = cadd(E3, O3w); a[7] = csub(E3, O3w);
}

__device__ __forceinline__ void twiddle8(float2 a[8], float ang) {
    float sv, cv; __sincosf(ang, &sv, &cv);
    float2 w1 = make_float2(cv, sv), w = w1;
    a[1] = cmul(a[1], w);
#pragma unroll
    for (int i = 2; i < 8; i++) { w = cmul(w, w1); a[i] = cmul(a[i], w); }
}

template <bool INV, int LOGS, bool POST>
__device__ __forceinline__ void stage_g(float2* z, int t) {
    constexpr int S = 1 << LOGS;
    int j = t & (S - 1);
    int base = ((t >> LOGS) << (LOGS + 3)) + j;
    float2 a[8];
#pragma unroll
    for (int i = 0; i < 8; i++) a[i] = z[sidx(base + i * S)];
    bool tw = (S > 1) && (j != 0);
    float ang = (INV ? 6.283185307179586f : -6.283185307179586f) * (float)j / (float)(8 * S);
    if (!POST && tw) twiddle8(a, ang);
    radix8<INV>(a);
    if (POST && tw) twiddle8(a, ang);
#pragma unroll
    for (int i = 0; i < 8; i++) z[sidx(base + i * S)] = a[i];
}

__device__ __forceinline__ void fwd_first_stage(float2* z, int t, float2 a[8]) {
    radix8<false>(a);
    if (t) twiddle8(a, -6.283185307179586f * (float)t / 4096.0f);
#pragma unroll
    for (int i = 0; i < 8; i++) z[sidx(t + i * 512)] = a[i];
}

// ---------------------------------------------------------------------------
// Kernel A: squash + DIF rfft(8192 packed) -> per-position table g_Tab
// ---------------------------------------------------------------------------
__global__ __launch_bounds__(512, 2) void build_kf_kernel(const float* __restrict__ kparam) {
    __shared__ float2 z[SMSZ];
    int t = threadIdx.x, h = blockIdx.x;
    const float2* kp2 = (const float2*)(kparam + (size_t)h * Ll);

    float2 a[8];
#pragma unroll
    for (int i = 0; i < 4; i++) {
        float2 v = kp2[t + 512 * i];
        float s0 = fabsf(v.x) - LAMBDA; float aa = (s0 > 0.f) ? copysignf(s0, v.x) : 0.f;
        float s1 = fabsf(v.y) - LAMBDA; float bb = (s1 > 0.f) ? copysignf(s1, v.y) : 0.f;
        a[i] = make_float2(aa, bb);
    }
#pragma unroll
    for (int i = 4; i < 8; i++) a[i] = make_float2(0.f, 0.f);
    fwd_first_stage(z, t, a);
    __syncthreads();
    stage_g<false, 6, true>(z, t); __syncthreads();
    stage_g<false, 3, true>(z, t); __syncthreads();
    stage_g<false, 0, true>(z, t); __syncthreads();

    float4* tab = g_Tab + (size_t)h * 4096;
    const float scale = 1.0f / (float)NC;
    for (int p = t; p < 4096; p += 512) {
        int k = rev4(p);
        float4 e;
        if (k == 0) {
            float2 Z0 = z[sidx(0)];
            float K0 = (Z0.x + Z0.y) * scale;
            float KN = (Z0.x - Z0.y) * scale;
            e = make_float4(0.5f * (K0 + KN), 0.f, 0.f, 0.5f * (K0 - KN));
        } else {
            int kk = (k <= 2048) ? k : 4096 - k;
            float2 Zk = z[sidx(rev4(kk))];
            float2 Zj = z[sidx(rev4(4096 - kk))];
            float2 E = make_float2(0.5f * (Zk.x + Zj.x),  0.5f * (Zk.y - Zj.y));
            float2 O = make_float2(0.5f * (Zk.y + Zj.y), -0.5f * (Zk.x - Zj.x));
            float sv, cv; __sincosf(-3.14159265358979f * (float)kk / (float)NC, &sv, &cv);
            float2 W  = make_float2(cv, sv);
            float2 Wj = make_float2(-cv, sv);
            float2 Kk = cscale(cadd(E, cmul(W, O)), scale);
            float2 Kj = cscale(cadd(conjf2(E), cmul(Wj, conjf2(O))), scale);
            float s = sv, c = cv;
            if (k <= 2048) {
                e.x = 0.5f * ((1.f + s) * Kk.x + (1.f - s) * Kj.x);
                e.y = 0.5f * ((1.f + s) * Kk.y - (1.f - s) * Kj.y);
                e.z = -0.5f * c * (Kk.y + Kj.y);
                e.w =  0.5f * c * (Kk.x - Kj.x);
            } else {
                e.x = 0.5f * ((1.f + s) * Kj.x + (1.f - s) * Kk.x);
                e.y = 0.5f * ((1.f + s) * Kj.y - (1.f - s) * Kk.y);
                e.z =  0.5f * c * (Kj.y + Kk.y);
                e.w = -0.5f * c * (Kj.x - Kk.x);
            }
        }
        tab[p] = e;
    }
}

// ---------------------------------------------------------------------------
// Kernel A2: W fp32 -> fp16 (once)
// ---------------------------------------------------------------------------
__global__ void split_w_kernel(const float* __restrict__ W) {
    int i = blockIdx.x * 256 + threadIdx.x;
    float4 w4 = *(const float4*)(W + 4 * (size_t)i);
    __half h0 = __float2half(w4.x);
    __half h1 = __float2half(w4.y);
    __half h2 = __float2half(w4.z);
    __half h3 = __float2half(w4.w);
    uint2 hp;
    hp.x = (uint32_t)__half_as_ushort(h0) | ((uint32_t)__half_as_ushort(h1) << 16);
    hp.y = (uint32_t)__half_as_ushort(h2) | ((uint32_t)__half_as_ushort(h3) << 16);
    *(uint2*)(g_Whi + 2 * (size_t)i) = hp;
}

// ---------------------------------------------------------------------------
// Kernel B: DIF fwd -> per-position pointwise (z->z2) -> DIT inv (last stage
// in regs) -> +D*u -> GELU -> fp16.  Round-11 kernel body; grid is now
// (b, h) so the 16 CTAs sharing one g_Tab h-slice are launch-adjacent
// (table read from DRAM once, then L2).
// ---------------------------------------------------------------------------
#define CONV_SMEM (2 * SMSZ * (int)sizeof(float2))   // 69632

__global__ __launch_bounds__(512, 3) void conv_kernel(const float* __restrict__ u,
                                                      const float* __restrict__ D) {
    extern __shared__ float2 zz[];
    float2* z  = zz;
    float2* z2 = zz + SMSZ;
    int t = threadIdx.x;
    int b = blockIdx.x;          // fast dim: same-h CTAs adjacent
    int h = blockIdx.y;
    const float2* u2 = (const float2*)(u + ((size_t)(b * Hh + h)) * Ll);

    {
        float2 a[8];
#pragma unroll
        for (int i = 0; i < 4; i++) a[i] = u2[t + 512 * i];
#pragma unroll
        for (int i = 4; i < 8; i++) a[i] = make_float2(0.f, 0.f);
        fwd_first_stage(z, t, a);
    }
    __syncthreads();
    stage_g<false, 6, true>(z, t); __syncthreads();
    stage_g<false, 3, true>(z, t); __syncthreads();
    stage_g<false, 0, true>(z, t); __syncthreads();

    const float4* tab = g_Tab + (size_t)h * 4096;
    for (int p = t; p < 4096; p += 512) {
        int q = rev4((4096 - rev4(p)) & 4095);
        float2 Zp = z[sidx(p)];
        float2 Zq = z[sidx(q)];
        float4 tA = tab[p];
        float nx = tA.x * Zp.x - tA.y * Zp.y + tA.z * Zq.x + tA.w * Zq.y;
        float ny = tA.x * Zp.y + tA.y * Zp.x + tA.w * Zq.x - tA.z * Zq.y;
        z2[sidx(p)] = make_float2(nx, ny);
    }
    __syncthreads();

    stage_g<true, 0, false>(z2, t); __syncthreads();
    stage_g<true, 3, false>(z2, t); __syncthreads();
    stage_g<true, 6, false>(z2, t); __syncthreads();

    float2 a[8];
#pragma unroll
    for (int i = 0; i < 8; i++) a[i] = z2[sidx(t + i * 512)];
    if (t) twiddle8(a, 6.283185307179586f * (float)t / 4096.0f);
    radix8<true>(a);

    float dcoef = D[h];
    uint32_t* yh = g_Yhi + ((size_t)(b * Hh + h)) * (Ll / 2);
    const float INV_SQRT2 = 0.70710678118654752f;
#pragma unroll
    for (int i = 0; i < 4; i++) {
        int n = t + 512 * i;
        float2 uv = u2[n];
        float y0 = a[i].x + dcoef * uv.x;
        float y1 = a[i].y + dcoef * uv.y;
        y0 = 0.5f * y0 * (1.0f + erff(y0 * INV_SQRT2));
        y1 = 0.5f * y1 * (1.0f + erff(y1 * INV_SQRT2));
        __half h0 = __float2half(y0);
        __half h1 = __float2half(y1);
        yh[n] = (uint32_t)__half_as_ushort(h0) | ((uint32_t)__half_as_ushort(h1) << 16);
    }
}

// ---------------------------------------------------------------------------
// Kernel C: HMMA fp16 GEMM, single term (Whi*Yhi), warp tile 64x32,
// CTA 128x128, 8 warps 2x4, 3-stage cp.async pipeline (round-11 validated)
// ---------------------------------------------------------------------------
#define HC 32
#define NHC 16
#define A_ST 80
#define ST_SZ 18432
#define GEMM_SMEM (3 * ST_SZ)   // 55296

__device__ __forceinline__ uint32_t smem_u32(const void* p) {
    uint32_t a;
    asm("{ .reg .u64 t; cvta.to.shared.u64 t, %1; cvt.u32.u64 %0, t; }" : "=r"(a) : "l"(p));
    return a;
}
__device__ __forceinline__ void cpa16(uint32_t dst, const void* src) {
    asm volatile("cp.async.cg.shared.global [%0], [%1], 16;" :: "r"(dst), "l"(src));
}
__device__ __forceinline__ void ldsm4(uint32_t r[4], uint32_t addr) {
    asm volatile("ldmatrix.sync.aligned.m8n8.x4.shared.b16 {%0,%1,%2,%3}, [%4];"
                 : "=r"(r[0]), "=r"(r[1]), "=r"(r[2]), "=r"(r[3]) : "r"(addr));
}
__device__ __forceinline__ void ldsm4t(uint32_t r[4], uint32_t addr) {
    asm volatile("ldmatrix.sync.aligned.m8n8.x4.trans.shared.b16 {%0,%1,%2,%3}, [%4];"
                 : "=r"(r[0]), "=r"(r[1]), "=r"(r[2]), "=r"(r[3]) : "r"(addr));
}
__device__ __forceinline__ void mma16816h(float c[4], const uint32_t a[4], const uint32_t b[2]) {
    asm volatile(
        "mma.sync.aligned.m16n8k16.row.col.f32.f16.f16.f32 "
        "{%0,%1,%2,%3}, {%4,%5,%6,%7}, {%8,%9}, {%0,%1,%2,%3};"
        : "+f"(c[0]), "+f"(c[1]), "+f"(c[2]), "+f"(c[3])
        : "r"(a[0]), "r"(a[1]), "r"(a[2]), "r"(a[3]), "r"(b[0]), "r"(b[1]));
}
__device__ __forceinline__ float silu_f(float x) { return x / (1.0f + __expf(-x)); }
__device__ __forceinline__ int bswz(int k, int cb) { return (cb & 8) | ((cb ^ k) & 7); }

__global__ __launch_bounds__(256, 2) void gemm_silu_kernel(const float* __restrict__ bias,
                                                           float* __restrict__ out) {
    extern __shared__ char smem[];
    uint32_t sb = smem_u32(smem);
    int tid = threadIdx.x;
    int wid = tid >> 5;
    int lane = tid & 31;

    int v0 = blockIdx.x * 128;           // vt fastest -> 4 CTAs share B tile in L2
    int l0 = blockIdx.y * 128;
    int b  = blockIdx.z;

    int wm = wid & 1;
    int wn = wid >> 1;

    const __half* Yh = (const __half*)g_Yhi;
    const __half* Wh = (const __half*)g_Whi;

    float acc[4][4][4];
#pragma unroll
    for (int i = 0; i < 4; i++)
#pragma unroll
        for (int j = 0; j < 4; j++)
#pragma unroll
            for (int q = 0; q < 4; q++) acc[i][j][q] = 0.f;

    int ar  = tid >> 1;
    int ab  = (tid & 1) * 2;
    int bk  = tid >> 4;
    int bcb = tid & 15;

    auto load_hc = [&](int hc, int s) {
        int k0 = hc * HC;
        uint32_t base = sb + s * ST_SZ;
#pragma unroll
        for (int i = 0; i < 2; i++) {
            int blk = ab + i;
            size_t ga = (size_t)(v0 + ar) * Hh + k0 + blk * 8;
            cpa16(base + ar * A_ST + blk * 16, Wh + ga);
        }
#pragma unroll
        for (int g = 0; g < 2; g++) {
            int k = bk + g * 16;
            size_t ge = ((size_t)(b * Hh) + k0 + k) * Ll + l0 + bcb * 8;
            cpa16(base + 10240 + k * 256 + bswz(k, bcb) * 16, Yh + ge);
        }
    };

    load_hc(0, 0);
    asm volatile("cp.async.commit_group;" ::: "memory");
    load_hc(1, 1);
    asm volatile("cp.async.commit_group;" ::: "memory");

    for (int hc = 0; hc < NHC; hc++) {
        if (hc < NHC - 1) {
            asm volatile("cp.async.wait_group 1;" ::: "memory");
        } else {
            asm volatile("cp.async.wait_group 0;" ::: "memory");
        }
        __syncthreads();
        if (hc + 2 < NHC) {
            load_hc(hc + 2, (hc + 2) % 3);
            asm volatile("cp.async.commit_group;" ::: "memory");
        }

        uint32_t abase = sb + (hc % 3) * ST_SZ;
        uint32_t bbase = abase + 10240;
#pragma unroll
        for (int ks = 0; ks < 2; ks++) {
            uint32_t bh[2][4];
#pragma unroll
            for (int g = 0; g < 2; g++) {
                int krow = ks * 16 + (lane & 15);
                int cb = wn * 4 + g * 2 + (lane >> 4);
                uint32_t baddr = bbase + krow * 256 + bswz(krow, cb) * 16;
                ldsm4t(bh[g], baddr);
            }
#pragma unroll
            for (int mt = 0; mt < 4; mt++) {
                int arow = wm * 64 + mt * 16 + (lane & 15);
                uint32_t aaddr = abase + arow * A_ST + ks * 32 + (lane >> 4) * 16;
                uint32_t ahf[4];
                ldsm4(ahf, aaddr);
#pragma unroll
                for (int nt = 0; nt < 4; nt++) {
                    const uint32_t* bhx = &bh[nt >> 1][(nt & 1) * 2];
                    mma16816h(acc[mt][nt], ahf, bhx);
                }
            }
        }
    }

    __syncthreads();
    int g = lane >> 2;
    int cq = (lane & 3) * 2;
#pragma unroll
    for (int mt = 0; mt < 4; mt++) {
        int vbase = v0 + wm * 64 + mt * 16 + g;
        float bv0 = bias[vbase];
        float bv1 = bias[vbase + 8];
        float* row0 = out + ((size_t)(b * Hh) + vbase) * Ll;
        float* row1 = row0 + 8 * Ll;
#pragma unroll
        for (int nt = 0; nt < 4; nt++) {
            int lc = l0 + wn * 32 + nt * 8 + cq;
            float2 o0, o1;
            o0.x = silu_f(acc[mt][nt][0] + bv0);
            o0.y = silu_f(acc[mt][nt][1] + bv0);
            o1.x = silu_f(acc[mt][nt][2] + bv1);
            o1.y = silu_f(acc[mt][nt][3] + bv1);
            *(float2*)(row0 + lc) = o0;
            *(float2*)(row1 + lc) = o1;
        }
    }
}

extern "C" void kernel_launch(void* const* d_in, const int* in_sizes, int n_in,
                              void* d_out, int out_size) {
    const float* u    = (const float*)d_in[0];   // (16, 512, 4096)
    const float* kern = (const float*)d_in[1];   // (1, 512, 4096)
    const float* D    = (const float*)d_in[2];   // (1, 512)
    const float* Wout = (const float*)d_in[3];   // (512, 512)
    const float* bout = (const float*)d_in[4];   // (512,)
    float* out = (float*)d_out;                  // (16, 512, 4096)

    cudaFuncSetAttribute(gemm_silu_kernel, cudaFuncAttributeMaxDynamicSharedMemorySize, GEMM_SMEM);
    cudaFuncSetAttribute(conv_kernel, cudaFuncAttributeMaxDynamicSharedMemorySize, CONV_SMEM);

    build_kf_kernel<<<Hh, 512>>>(kern);
    split_w_kernel<<<256, 256>>>(Wout);
    conv_kernel<<<dim3(Bb, Hh), 512, CONV_SMEM>>>(u, D);
    gemm_silu_kernel<<<dim3(4, 32, 16), 256, GEMM_SMEM>>>(bout, out);
}

// round 16
// speedup vs baseline: 1.1022x; 1.0030x over previous
#include <cuda_runtime.h>
#include <cuda_bf16.h>
#include <cuda_fp16.h>
#include <math.h>
#include <stdint.h>

#define Bb 16
#define Hh 512
#define Ll 4096
#define NC 4096
#define LAMBDA 0.001f

// Scratch (no runtime allocation allowed)
__device__ float4   g_Tab[(size_t)Hh * 4096];               // per-POSITION pointwise table
__device__ uint32_t g_Yhi[(size_t)Bb * Hh * Ll / 2];        // fp16x2 of gelu(conv+skip)
__device__ uint32_t g_Whi[Hh * Hh / 2];                     // W fp16x2, row-major [v][k]

__device__ __forceinline__ float2 cadd(float2 a, float2 b) { return make_float2(a.x + b.x, a.y + b.y); }
__device__ __forceinline__ float2 csub(float2 a, float2 b) { return make_float2(a.x - b.x, a.y - b.y); }
__device__ __forceinline__ float2 cmul(float2 a, float2 b) {
    return make_float2(a.x * b.x - a.y * b.y, a.x * b.y + a.y * b.x);
}
__device__ __forceinline__ float2 conjf2(float2 a) { return make_float2(a.x, -a.y); }
__device__ __forceinline__ float2 cscale(float2 a, float s) { return make_float2(a.x * s, a.y * s); }

__device__ __forceinline__ int sidx(int n) { return n + (n >> 4); }
#define SMSZ (4096 + 256)

// 4-digit octal reversal (12-bit), involutive
__device__ __forceinline__ int rev4(int k) {
    return ((k & 7) << 9) | (((k >> 3) & 7) << 6) | (((k >> 6) & 7) << 3) | ((k >> 9) & 7);
}

// ---------------------------------------------------------------------------
// radix-8 FFT machinery (round-11 validated; serial twiddle chain = low regs)
// ---------------------------------------------------------------------------
template <bool INV>
__device__ __forceinline__ void radix8(float2 a[8]) {
    const float C = 0.70710678118654752440f;
    float2 t0 = cadd(a[0], a[4]);
    float2 t1 = csub(a[0], a[4]);
    float2 t2 = cadd(a[2], a[6]);
    float2 t3;
    { float2 d = csub(a[2], a[6]); t3 = INV ? make_float2(-d.y, d.x) : make_float2(d.y, -d.x); }
    float2 E0 = cadd(t0, t2), E2 = csub(t0, t2);
    float2 E1 = cadd(t1, t3), E3 = csub(t1, t3);
    float2 s0 = cadd(a[1], a[5]);
    float2 s1 = csub(a[1], a[5]);
    float2 s2 = cadd(a[3], a[7]);
    float2 s3;
    { float2 d = csub(a[3], a[7]); s3 = INV ? make_float2(-d.y, d.x) : make_float2(d.y, -d.x); }
    float2 O0 = cadd(s0, s2), O2 = csub(s0, s2);
    float2 O1 = cadd(s1, s3), O3 = csub(s1, s3);
    float2 O1w, O2w, O3w;
    if (!INV) {
        O1w = make_float2(C * (O1.x + O1.y), C * (O1.y - O1.x));
        O2w = make_float2(O2.y, -O2.x);
        O3w = make_float2(C * (O3.y - O3.x), -C * (O3.x + O3.y));
    } else {
        O1w = make_float2(C * (O1.x - O1.y), C * (O1.y + O1.x));
        O2w = make_float2(-O2.y, O2.x);
        O3w = make_float2(-C * (O3.x + O3.y), C * (O3.x - O3.y));
    }
    a[0] = cadd(E0, O0);  a[4] = csub(E0, O0);
    a[1] = cadd(E1, O1w); a[5] = csub(E1, O1w);
    a[2] = cadd(E2, O2w); a[6] = csub(E2, O2w);
    a[3] = cadd(E3, O3w); a[7] = csub(E3, O3w);
}

// inverse radix-8 computing ONLY outputs 0..3 (upper half discarded by caller)
__device__ __forceinline__ void radix8_inv_low(float2 a[8]) {
    const float C = 0.70710678118654752440f;
    float2 t0 = cadd(a[0], a[4]);
    float2 t1 = csub(a[0], a[4]);
    float2 t2 = cadd(a[2], a[6]);
    float2 t3;
    { float2 d = csub(a[2], a[6]); t3 = make_float2(-d.y, d.x); }
    float2 E0 = cadd(t0, t2), E2 = csub(t0, t2);
    float2 E1 = cadd(t1, t3), E3 = csub(t1, t3);
    float2 s0 = cadd(a[1], a[5]);
    float2 s1 = csub(a[1], a[5]);
    float2 s2 = cadd(a[3], a[7]);
    float2 s3;
    { float2 d = csub(a[3], a[7]); s3 = make_float2(-d.y, d.x); }
    float2 O0 = cadd(s0, s2), O2 = csub(s0, s2);
    float2 O1 = cadd(s1, s3), O3 = csub(s1, s3);
    float2 O1w = make_float2(C * (O1.x - O1.y), C * (O1.y + O1.x));
    float2 O2w = make_float2(-O2.y, O2.x);
    float2 O3w = make_float2(-C * (O3.x + O3.y), C * (O3.x - O3.y));
    a[0] = cadd(E0, O0);
    a[1] = cadd(E1, O1w);
    a[2] = cadd(E2, O2w);
    a[3] = cadd(E3, O3w);
}

__device__ __forceinline__ void twiddle8(float2 a[8], float ang) {
    float sv, cv; __sincosf(ang, &sv, &cv);
    float2 w1 = make_float2(cv, sv), w = w1;
    a[1] = cmul(a[1], w);
#pragma unroll
    for (int i = 2; i < 8; i++) { w = cmul(w, w1); a[i] = cmul(a[i], w); }
}

template <bool INV, int LOGS, bool POST>
__device__ __forceinline__ void stage_g(float2* z, int t) {
    constexpr int S = 1 << LOGS;
    int j = t & (S - 1);
    int base = ((t >> LOGS) << (LOGS + 3)) + j;
    float2 a[8];
#pragma unroll
    for (int i = 0; i < 8; i++) a[i] = z[sidx(base + i * S)];
    bool tw = (S > 1) && (j != 0);
    float ang = (INV ? 6.283185307179586f : -6.283185307179586f) * (float)j / (float)(8 * S);
    if (!POST && tw) twiddle8(a, ang);
    radix8<INV>(a);
    if (POST && tw) twiddle8(a, ang);
#pragma unroll
    for (int i = 0; i < 8; i++) z[sidx(base + i * S)] = a[i];
}

__device__ __forceinline__ void fwd_first_stage(float2* z, int t, float2 a[8]) {
    radix8<false>(a);
    if (t) twiddle8(a, -6.283185307179586f * (float)t / 4096.0f);
#pragma unroll
    for (int i = 0; i < 8; i++) z[sidx(t + i * 512)] = a[i];
}

// ---------------------------------------------------------------------------
// Kernel A: squash + DIF rfft(8192 packed) -> per-position table g_Tab
// ---------------------------------------------------------------------------
__global__ __launch_bounds__(512, 2) void build_kf_kernel(const float* __restrict__ kparam) {
    __shared__ float2 z[SMSZ];
    int t = threadIdx.x, h = blockIdx.x;
    const float2* kp2 = (const float2*)(kparam + (size_t)h * Ll);

    float2 a[8];
#pragma unroll
    for (int i = 0; i < 4; i++) {
        float2 v = kp2[t + 512 * i];
        float s0 = fabsf(v.x) - LAMBDA; float aa = (s0 > 0.f) ? copysignf(s0, v.x) : 0.f;
        float s1 = fabsf(v.y) - LAMBDA; float bb = (s1 > 0.f) ? copysignf(s1, v.y) : 0.f;
        a[i] = make_float2(aa, bb);
    }
#pragma unroll
    for (int i = 4; i < 8; i++) a[i] = make_float2(0.f, 0.f);
    fwd_first_stage(z, t, a);
    __syncthreads();
    stage_g<false, 6, true>(z, t); __syncthreads();
    stage_g<false, 3, true>(z, t); __syncwarp();   // S=8 -> S=1: octet-local
    stage_g<false, 0, true>(z, t); __syncthreads();

    float4* tab = g_Tab + (size_t)h * 4096;
    const float scale = 1.0f / (float)NC;
    for (int p = t; p < 4096; p += 512) {
        int k = rev4(p);
        float4 e;
        if (k == 0) {
            float2 Z0 = z[sidx(0)];
            float K0 = (Z0.x + Z0.y) * scale;
            float KN = (Z0.x - Z0.y) * scale;
            e = make_float4(0.5f * (K0 + KN), 0.f, 0.f, 0.5f * (K0 - KN));
        } else {
            int kk = (k <= 2048) ? k : 4096 - k;
            float2 Zk = z[sidx(rev4(kk))];
            float2 Zj = z[sidx(rev4(4096 - kk))];
            float2 E = make_float2(0.5f * (Zk.x + Zj.x),  0.5f * (Zk.y - Zj.y));
            float2 O = make_float2(0.5f * (Zk.y + Zj.y), -0.5f * (Zk.x - Zj.x));
            float sv, cv; __sincosf(-3.14159265358979f * (float)kk / (float)NC, &sv, &cv);
            float2 W  = make_float2(cv, sv);
            float2 Wj = make_float2(-cv, sv);
            float2 Kk = cscale(cadd(E, cmul(W, O)), scale);
            float2 Kj = cscale(cadd(conjf2(E), cmul(Wj, conjf2(O))), scale);
            float s = sv, c = cv;
            if (k <= 2048) {
                e.x = 0.5f * ((1.f + s) * Kk.x + (1.f - s) * Kj.x);
                e.y = 0.5f * ((1.f + s) * Kk.y - (1.f - s) * Kj.y);
                e.z = -0.5f * c * (Kk.y + Kj.y);
                e.w =  0.5f * c * (Kk.x - Kj.x);
            } else {
                e.x = 0.5f * ((1.f + s) * Kj.x + (1.f - s) * Kk.x);
                e.y = 0.5f * ((1.f + s) * Kj.y - (1.f - s) * Kk.y);
                e.z =  0.5f * c * (Kj.y + Kk.y);
                e.w = -0.5f * c * (Kj.x - Kk.x);
            }
        }
        tab[p] = e;
    }
}

// ---------------------------------------------------------------------------
// Kernel A2: W fp32 -> fp16 (once)
// ---------------------------------------------------------------------------
__global__ void split_w_kernel(const float* __restrict__ W) {
    int i = blockIdx.x * 256 + threadIdx.x;
    float4 w4 = *(const float4*)(W + 4 * (size_t)i);
    __half h0 = __float2half(w4.x);
    __half h1 = __float2half(w4.y);
    __half h2 = __float2half(w4.z);
    __half h3 = __float2half(w4.w);
    uint2 hp;
    hp.x = (uint32_t)__half_as_ushort(h0) | ((uint32_t)__half_as_ushort(h1) << 16);
    hp.y = (uint32_t)__half_as_ushort(h2) | ((uint32_t)__half_as_ushort(h3) << 16);
    *(uint2*)(g_Whi + 2 * (size_t)i) = hp;
}

// ---------------------------------------------------------------------------
// Kernel B: DIF fwd -> per-position pointwise (z->z2) -> DIT inv (pruned last
// stage in regs) -> +D*u -> GELU -> fp16.  Round-11 base; barrier demotions.
// ---------------------------------------------------------------------------
#define CONV_SMEM (2 * SMSZ * (int)sizeof(float2))   // 69632

__global__ __launch_bounds__(512, 3) void conv_kernel(const float* __restrict__ u,
                                                      const float* __restrict__ D) {
    extern __shared__ float2 zz[];
    float2* z  = zz;
    float2* z2 = zz + SMSZ;
    int t = threadIdx.x, h = blockIdx.x, b = blockIdx.y;
    const float2* u2 = (const float2*)(u + ((size_t)(b * Hh + h)) * Ll);

    {
        float2 a[8];
#pragma unroll
        for (int i = 0; i < 4; i++) a[i] = u2[t + 512 * i];
#pragma unroll
        for (int i = 4; i < 8; i++) a[i] = make_float2(0.f, 0.f);
        fwd_first_stage(z, t, a);
    }
    __syncthreads();
    stage_g<false, 6, true>(z, t); __syncthreads();
    stage_g<false, 3, true>(z, t); __syncwarp();   // S=8 -> S=1: octet-local
    stage_g<false, 0, true>(z, t); __syncthreads();

    const float4* tab = g_Tab + (size_t)h * 4096;
    for (int p = t; p < 4096; p += 512) {
        int q = rev4((4096 - rev4(p)) & 4095);
        float2 Zp = z[sidx(p)];
        float2 Zq = z[sidx(q)];
        float4 tA = tab[p];
        float nx = tA.x * Zp.x - tA.y * Zp.y + tA.z * Zq.x + tA.w * Zq.y;
        float ny = tA.x * Zp.y + tA.y * Zp.x + tA.w * Zq.x - tA.z * Zq.y;
        z2[sidx(p)] = make_float2(nx, ny);
    }
    __syncthreads();

    stage_g<true, 0, false>(z2, t); __syncwarp();  // S=1 -> S=8: octet-local
    stage_g<true, 3, false>(z2, t); __syncthreads();
    stage_g<true, 6, false>(z2, t); __syncthreads();

    float2 a[8];
#pragma unroll
    for (int i = 0; i < 8; i++) a[i] = z2[sidx(t + i * 512)];
    if (t) twiddle8(a, 6.283185307179586f * (float)t / 4096.0f);
    radix8_inv_low(a);     // only outputs 0..3 needed (n < 2048)

    float dcoef = D[h];
    uint32_t* yh = g_Yhi + ((size_t)(b * Hh + h)) * (Ll / 2);
    const float INV_SQRT2 = 0.70710678118654752f;
#pragma unroll
    for (int i = 0; i < 4; i++) {
        int n = t + 512 * i;
        float2 uv = u2[n];
        float y0 = a[i].x + dcoef * uv.x;
        float y1 = a[i].y + dcoef * uv.y;
        y0 = 0.5f * y0 * (1.0f + erff(y0 * INV_SQRT2));
        y1 = 0.5f * y1 * (1.0f + erff(y1 * INV_SQRT2));
        __half h0 = __float2half(y0);
        __half h1 = __float2half(y1);
        yh[n] = (uint32_t)__half_as_ushort(h0) | ((uint32_t)__half_as_ushort(h1) << 16);
    }
}

// ---------------------------------------------------------------------------
// Kernel C: HMMA fp16 GEMM, single term (Whi*Yhi), warp tile 64x32,
// CTA 128x128, 8 warps 2x4, 3-stage cp.async pipeline (round-11 validated)
// ---------------------------------------------------------------------------
#define HC 32
#define NHC 16
#define A_ST 80
#define ST_SZ 18432
#define GEMM_SMEM (3 * ST_SZ)   // 55296

__device__ __forceinline__ uint32_t smem_u32(const void* p) {
    uint32_t a;
    asm("{ .reg .u64 t; cvta.to.shared.u64 t, %1; cvt.u32.u64 %0, t; }" : "=r"(a) : "l"(p));
    return a;
}
__device__ __forceinline__ void cpa16(uint32_t dst, const void* src) {
    asm volatile("cp.async.cg.shared.global [%0], [%1], 16;" :: "r"(dst), "l"(src));
}
__device__ __forceinline__ void ldsm4(uint32_t r[4], uint32_t addr) {
    asm volatile("ldmatrix.sync.aligned.m8n8.x4.shared.b16 {%0,%1,%2,%3}, [%4];"
                 : "=r"(r[0]), "=r"(r[1]), "=r"(r[2]), "=r"(r[3]) : "r"(addr));
}
__device__ __forceinline__ void ldsm4t(uint32_t r[4], uint32_t addr) {
    asm volatile("ldmatrix.sync.aligned.m8n8.x4.trans.shared.b16 {%0,%1,%2,%3}, [%4];"
                 : "=r"(r[0]), "=r"(r[1]), "=r"(r[2]), "=r"(r[3]) : "r"(addr));
}
__device__ __forceinline__ void mma16816h(float c[4], const uint32_t a[4], const uint32_t b[2]) {
    asm volatile(
        "mma.sync.aligned.m16n8k16.row.col.f32.f16.f16.f32 "
        "{%0,%1,%2,%3}, {%4,%5,%6,%7}, {%8,%9}, {%0,%1,%2,%3};"
        : "+f"(c[0]), "+f"(c[1]), "+f"(c[2]), "+f"(c[3])
        : "r"(a[0]), "r"(a[1]), "r"(a[2]), "r"(a[3]), "r"(b[0]), "r"(b[1]));
}
__device__ __forceinline__ float silu_f(float x) { return x / (1.0f + __expf(-x)); }
__device__ __forceinline__ int bswz(int k, int cb) { return (cb & 8) | ((cb ^ k) & 7); }

__global__ __launch_bounds__(256, 2) void gemm_silu_kernel(const float* __restrict__ bias,
                                                           float* __restrict__ out) {
    extern __shared__ char smem[];
    uint32_t sb = smem_u32(smem);
    int tid = threadIdx.x;
    int wid = tid >> 5;
    int lane = tid & 31;

    int v0 = blockIdx.x * 128;           // vt fastest -> 4 CTAs share B tile in L2
    int l0 = blockIdx.y * 128;
    int b  = blockIdx.z;

    int wm = wid & 1;
    int wn = wid >> 1;

    const __half* Yh = (const __half*)g_Yhi;
    const __half* Wh = (const __half*)g_Whi;

    float acc[4][4][4];
#pragma unroll
    for (int i = 0; i < 4; i++)
#pragma unroll
        for (int j = 0; j < 4; j++)
#pragma unroll
            for (int q = 0; q < 4; q++) acc[i][j][q] = 0.f;

    int ar  = tid >> 1;
    int ab  = (tid & 1) * 2;
    int bk  = tid >> 4;
    int bcb = tid & 15;

    auto load_hc = [&](int hc, int s) {
        int k0 = hc * HC;
        uint32_t base = sb + s * ST_SZ;
#pragma unroll
        for (int i = 0; i < 2; i++) {
            int blk = ab + i;
            size_t ga = (size_t)(v0 + ar) * Hh + k0 + blk * 8;
            cpa16(base + ar * A_ST + blk * 16, Wh + ga);
        }
#pragma unroll
        for (int g = 0; g < 2; g++) {
            int k = bk + g * 16;
            size_t ge = ((size_t)(b * Hh) + k0 + k) * Ll + l0 + bcb * 8;
            cpa16(base + 10240 + k * 256 + bswz(k, bcb) * 16, Yh + ge);
        }
    };

    load_hc(0, 0);
    asm volatile("cp.async.commit_group;" ::: "memory");
    load_hc(1, 1);
    asm volatile("cp.async.commit_group;" ::: "memory");

    for (int hc = 0; hc < NHC; hc++) {
        if (hc < NHC - 1) {
            asm volatile("cp.async.wait_group 1;" ::: "memory");
        } else {
            asm volatile("cp.async.wait_group 0;" ::: "memory");
        }
        __syncthreads();
        if (hc + 2 < NHC) {
            load_hc(hc + 2, (hc + 2) % 3);
            asm volatile("cp.async.commit_group;" ::: "memory");
        }

        uint32_t abase = sb + (hc % 3) * ST_SZ;
        uint32_t bbase = abase + 10240;
#pragma unroll
        for (int ks = 0; ks < 2; ks++) {
            uint32_t bh[2][4];
#pragma unroll
            for (int g = 0; g < 2; g++) {
                int krow = ks * 16 + (lane & 15);
                int cb = wn * 4 + g * 2 + (lane >> 4);
                uint32_t baddr = bbase + krow * 256 + bswz(krow, cb) * 16;
                ldsm4t(bh[g], baddr);
            }
#pragma unroll
            for (int mt = 0; mt < 4; mt++) {
                int arow = wm * 64 + mt * 16 + (lane & 15);
                uint32_t aaddr = abase + arow * A_ST + ks * 32 + (lane >> 4) * 16;
                uint32_t ahf[4];
                ldsm4(ahf, aaddr);
#pragma unroll
                for (int nt = 0; nt < 4; nt++) {
                    const uint32_t* bhx = &bh[nt >> 1][(nt & 1) * 2];
                    mma16816h(acc[mt][nt], ahf, bhx);
                }
            }
        }
    }

    __syncthreads();
    int g = lane >> 2;
    int cq = (lane & 3) * 2;
#pragma unroll
    for (int mt = 0; mt < 4; mt++) {
        int vbase = v0 + wm * 64 + mt * 16 + g;
        float bv0 = bias[vbase];
        float bv1 = bias[vbase + 8];
        float* row0 = out + ((size_t)(b * Hh) + vbase) * Ll;
        float* row1 = row0 + 8 * Ll;
#pragma unroll
        for (int nt = 0; nt < 4; nt++) {
            int lc = l0 + wn * 32 + nt * 8 + cq;
            float2 o0, o1;
            o0.x = silu_f(acc[mt][nt][0] + bv0);
            o0.y = silu_f(acc[mt][nt][1] + bv0);
            o1.x = silu_f(acc[mt][nt][2] + bv1);
            o1.y = silu_f(acc[mt][nt][3] + bv1);
            *(float2*)(row0 + lc) = o0;
            *(float2*)(row1 + lc) = o1;
        }
    }
}

extern "C" void kernel_launch(void* const* d_in, const int* in_sizes, int n_in,
                              void* d_out, int out_size) {
    const float* u    = (const float*)d_in[0];   // (16, 512, 4096)
    const float* kern = (const float*)d_in[1];   // (1, 512, 4096)
    const float* D    = (const float*)d_in[2];   // (1, 512)
    const float* Wout = (const float*)d_in[3];   // (512, 512)
    const float* bout = (const float*)d_in[4];   // (512,)
    float* out = (float*)d_out;                  // (16, 512, 4096)

    cudaFuncSetAttribute(gemm_silu_kernel, cudaFuncAttributeMaxDynamicSharedMemorySize, GEMM_SMEM);
    cudaFuncSetAttribute(conv_kernel, cudaFuncAttributeMaxDynamicSharedMemorySize, CONV_SMEM);

    build_kf_kernel<<<Hh, 512>>>(kern);
    split_w_kernel<<<256, 256>>>(Wout);
    conv_kernel<<<dim3(Hh, Bb), 512, CONV_SMEM>>>(u, D);
    gemm_silu_kernel<<<dim3(4, 32, 16), 256, GEMM_SMEM>>>(bout, out);
}